// round 14
// baseline (speedup 1.0000x reference)
#include <cuda_runtime.h>
#include <cstdint>

#define N_NODES 100000
#define N_EDGES 800000
#define ANNOT 92
#define HID 64
#define N_STEPS 8
#define N_IDX 20000
#define TILE_M 128
#define N_TILES ((N_NODES + TILE_M - 1) / TILE_M)   // 782
#define PAD 132

typedef unsigned long long u64;

// ---- scratch (no allocations allowed) ----
__device__ float g_h[N_NODES * HID];
__device__ float g_m[N_NODES * HID];
__device__ float g_aggr[N_NODES * HID];
__device__ float g_wpack[256 * 128];         // [n=256][k=128], tf32-rounded
__device__ float g_wgT[N_STEPS * HID * HID]; // [t][n=64][k=64] = Wg^T, tf32-rounded

// ---- helpers ----
__device__ __forceinline__ u64 ffma2(u64 a, u64 b, u64 c) {
    u64 d; asm("fma.rn.f32x2 %0, %1, %2, %3;" : "=l"(d) : "l"(a), "l"(b), "l"(c)); return d;
}
__device__ __forceinline__ u64 dup2(float v) {
    unsigned u = __float_as_uint(v); u64 d;
    asm("mov.b64 %0, {%1, %2};" : "=l"(d) : "r"(u), "r"(u)); return d;
}
__device__ __forceinline__ float lo2(u64 v) { return __uint_as_float((unsigned)v); }
__device__ __forceinline__ float hi2(u64 v) { return __uint_as_float((unsigned)(v >> 32)); }
__device__ __forceinline__ float sigm(float x) { return 1.f / (1.f + __expf(-x)); }
__device__ __forceinline__ float tanh_f(float x) { return 1.f - 2.f / (__expf(2.f * x) + 1.f); }
__device__ __forceinline__ uint32_t tf32r(float f) {
    uint32_t u; asm("cvt.rna.tf32.f32 %0, %1;" : "=r"(u) : "f"(f)); return u;
}
__device__ __forceinline__ float tf32f(float f) { return __uint_as_float(tf32r(f)); }

// m16n8k8 tf32 mma: C(4 f32) += A(4 b32) * B(2 b32)
__device__ __forceinline__ void mma8(float* c, const uint32_t* a, const uint32_t* b) {
    asm("mma.sync.aligned.m16n8k8.row.col.f32.tf32.tf32.f32 "
        "{%0,%1,%2,%3}, {%4,%5,%6,%7}, {%8,%9}, {%0,%1,%2,%3};"
        : "+f"(c[0]), "+f"(c[1]), "+f"(c[2]), "+f"(c[3])
        : "r"(a[0]), "r"(a[1]), "r"(a[2]), "r"(a[3]), "r"(b[0]), "r"(b[1]));
}

// =====================================================================
// pack: g_wpack [r|z|i_n|h_n](256)x(k=128=[ih|hh]), g_wgT (tf32-rounded)
// =====================================================================
__global__ void pack_kernel(const float* __restrict__ w_ih, const float* __restrict__ w_hh,
                            const float* __restrict__ W_g) {
    int i = blockIdx.x * blockDim.x + threadIdx.x;
    if (i < 256 * 128) {
        int n = i >> 7, k = i & 127;
        float v = 0.f;
        if (n < 64)        v = (k < 64) ? w_ih[n * 64 + k]            : w_hh[n * 64 + (k - 64)];
        else if (n < 128)  { int j = n - 64;  v = (k < 64) ? w_ih[(64 + j) * 64 + k] : w_hh[(64 + j) * 64 + (k - 64)]; }
        else if (n < 192)  { int j = n - 128; v = (k < 64) ? w_ih[(128 + j) * 64 + k] : 0.f; }
        else               { int j = n - 192; v = (k < 64) ? 0.f : w_hh[(128 + j) * 64 + (k - 64)]; }
        g_wpack[i] = tf32f(v);
    }
    int i2 = i - 256 * 128;
    if (i2 >= 0 && i2 < N_STEPS * 64 * 64) {
        int t = i2 >> 12, r = i2 & 4095, n = r >> 6, k = r & 63;
        g_wgT[i2] = tf32f(W_g[t * 4096 + k * 64 + n]);
    }
}

// =====================================================================
// reduce: h = x @ W_red + b_red  (FFMA2 path)
// =====================================================================
#define RNW 16
#define RNT 2
__global__ __launch_bounds__(512) void reduce_kernel(
    const float* __restrict__ x, const float* __restrict__ W,
    const float* __restrict__ b, float* __restrict__ h) {
    extern __shared__ char smraw[];
    float* s_w = (float*)smraw;
    u64* s_x = (u64*)(s_w + ANNOT * HID);
    int tid = threadIdx.x, lane = tid & 31, warp = tid >> 5;
    for (int i = tid; i < ANNOT * HID; i += blockDim.x) s_w[i] = W[i];
    __syncthreads();
    u64* my_x = s_x + warp * (RNT * ANNOT);
    int j0 = lane * 2;
    u64 bias = *(const u64*)(b + j0);
    int stride = gridDim.x * RNW * RNT;
    for (int base = (blockIdx.x * RNW + warp) * RNT; base < N_NODES; base += stride) {
        for (int t = 0; t < RNT; t++) {
            int node = base + t; if (node >= N_NODES) node = N_NODES - 1;
            const float* xr = x + (size_t)node * ANNOT;
            my_x[t * ANNOT + lane]      = dup2(xr[lane]);
            my_x[t * ANNOT + 32 + lane] = dup2(xr[32 + lane]);
            if (lane < ANNOT - 64) my_x[t * ANNOT + 64 + lane] = dup2(xr[64 + lane]);
        }
        __syncwarp();
        u64 acc[RNT];
        #pragma unroll
        for (int t = 0; t < RNT; t++) acc[t] = bias;
        #pragma unroll 4
        for (int k = 0; k < ANNOT; k++) {
            u64 w = *(const u64*)(s_w + k * HID + j0);
            #pragma unroll
            for (int t = 0; t < RNT; t++) acc[t] = ffma2(my_x[t * ANNOT + k], w, acc[t]);
        }
        #pragma unroll
        for (int t = 0; t < RNT; t++) {
            int node = base + t;
            if (node < N_NODES)
                *(float2*)(h + (size_t)node * HID + j0) = make_float2(lo2(acc[t]), hi2(acc[t]));
        }
        __syncwarp();
    }
}

// =====================================================================
// transform0: m = h @ W_g[0], zero aggr (step 0 only; FFMA2)
// =====================================================================
#define TNW 16
#define TNT 4
__global__ __launch_bounds__(512) void transform_kernel(
    const float* __restrict__ h, const float* __restrict__ Wg,
    float* __restrict__ m, float* __restrict__ aggr) {
    extern __shared__ char smraw[];
    float* s_w = (float*)smraw;
    u64* s_h = (u64*)(s_w + HID * HID);
    int tid = threadIdx.x, lane = tid & 31, warp = tid >> 5;
    for (int i = tid; i < HID * HID; i += blockDim.x) s_w[i] = Wg[i];
    __syncthreads();
    u64* my_h = s_h + warp * (TNT * HID);
    int j0 = lane * 2;
    int stride = gridDim.x * TNW * TNT;
    for (int base = (blockIdx.x * TNW + warp) * TNT; base < N_NODES; base += stride) {
        for (int t = 0; t < TNT; t++) {
            int node = base + t; if (node >= N_NODES) node = N_NODES - 1;
            const float* hr = h + (size_t)node * HID;
            my_h[t * HID + lane]      = dup2(hr[lane]);
            my_h[t * HID + 32 + lane] = dup2(hr[32 + lane]);
        }
        __syncwarp();
        u64 acc[TNT] = {0ull, 0ull, 0ull, 0ull};
        #pragma unroll 4
        for (int k = 0; k < HID; k++) {
            u64 w = *(const u64*)(s_w + k * HID + j0);
            #pragma unroll
            for (int t = 0; t < TNT; t++) acc[t] = ffma2(my_h[t * HID + k], w, acc[t]);
        }
        #pragma unroll
        for (int t = 0; t < TNT; t++) {
            int node = base + t;
            if (node < N_NODES) {
                *(float2*)(m    + (size_t)node * HID + j0) = make_float2(lo2(acc[t]), hi2(acc[t]));
                *(float2*)(aggr + (size_t)node * HID + j0) = make_float2(0.f, 0.f);
            }
        }
        __syncwarp();
    }
}

// =====================================================================
// scatter: aggr[dst] += m[src], float4 vector atomics
// =====================================================================
__global__ __launch_bounds__(256) void scatter_kernel(
    const float* __restrict__ m, const int* __restrict__ ei,
    float* __restrict__ aggr) {
    unsigned tid = blockIdx.x * blockDim.x + threadIdx.x;
    unsigned e = tid >> 4, p = tid & 15;
    if (e >= N_EDGES) return;
    int s = ei[e];
    int d = ei[N_EDGES + e];
    float4 v = ((const float4*)(m + (size_t)s * HID))[p];
    atomicAdd((float4*)(aggr + (size_t)d * HID + p * 4), v);
}

// =====================================================================
// GRU via mma.sync tf32. A-fragment order fixed:
//   a0=(r,c)  a1=(r+8,c)  a2=(r,c+4)  a3=(r+8,c+4)   [PTX m16n8k8.tf32]
// =====================================================================
#define SM_A 0
#define SM_B 67584
#define SM_C 135168
#define SM_BIAS 202752
#define SM_TOTAL 203776

__global__ __launch_bounds__(256) void gru_tc_kernel(
    float* __restrict__ aggr, float* __restrict__ h, float* __restrict__ m,
    const float* __restrict__ wpack, const float* __restrict__ wgT,
    const float* __restrict__ b_ih, const float* __restrict__ b_hh, int has_next) {
    extern __shared__ char smraw[];
    float* s_a = (float*)(smraw + SM_A);
    float* s_b = (float*)(smraw + SM_B);
    float* s_c = (float*)(smraw + SM_C);
    float* sb  = (float*)(smraw + SM_BIAS);   // [256]: r,z,i,hn biases
    int tid = threadIdx.x, lane = tid & 31, wid = tid >> 5;
    int warpM = wid >> 2, warpN = wid & 3;    // 2 x 4 warp grid for MMA1
    int base = blockIdx.x * TILE_M;

    // ---- stage A = [aggr|h] (tf32-rounded), 128x128 ----
    for (int i = tid; i < 128 * 32; i += 256) {
        int row = i >> 5, q = i & 31;
        int node = base + row; if (node >= N_NODES) node = N_NODES - 1;
        float4 v = (q < 16) ? ((const float4*)aggr)[node * 16 + q]
                            : ((const float4*)h)[node * 16 + (q - 16)];
        float* dst = s_a + row * PAD + q * 4;
        dst[0] = tf32f(v.x); dst[1] = tf32f(v.y); dst[2] = tf32f(v.z); dst[3] = tf32f(v.w);
    }
    // ---- stage B half0 (wpack rows 0..127: r|z) ----
    for (int i = tid; i < 128 * 32; i += 256) {
        int row = i >> 5, q = i & 31;
        *(float4*)(s_b + row * PAD + q * 4) = ((const float4*)wpack)[row * 32 + q];
    }
    if (tid < 64) {
        sb[tid]       = b_ih[tid] + b_hh[tid];
        sb[64 + tid]  = b_ih[64 + tid] + b_hh[64 + tid];
        sb[128 + tid] = b_ih[128 + tid];
        sb[192 + tid] = b_hh[128 + tid];
    }
    __syncthreads();

    float c[4][4][4];
    // ================= MMA1 half 0 (cols 0..127: r_sum | z_sum) =================
    #pragma unroll
    for (int mt = 0; mt < 4; mt++)
        #pragma unroll
        for (int nt = 0; nt < 4; nt++)
            #pragma unroll
            for (int i = 0; i < 4; i++) c[mt][nt][i] = 0.f;
    #pragma unroll 4
    for (int kt = 0; kt < 16; kt++) {
        int kc = kt * 8 + (lane & 3);
        uint32_t af[4][4], bf[4][2];
        #pragma unroll
        for (int mt = 0; mt < 4; mt++) {
            const float* pa = s_a + (warpM * 64 + mt * 16 + (lane >> 2)) * PAD;
            af[mt][0] = __float_as_uint(pa[kc]);
            af[mt][1] = __float_as_uint(pa[8 * PAD + kc]);
            af[mt][2] = __float_as_uint(pa[kc + 4]);
            af[mt][3] = __float_as_uint(pa[8 * PAD + kc + 4]);
        }
        #pragma unroll
        for (int nt = 0; nt < 4; nt++) {
            const float* pb = s_b + (warpN * 32 + nt * 8 + (lane >> 2)) * PAD;
            bf[nt][0] = __float_as_uint(pb[kc]);
            bf[nt][1] = __float_as_uint(pb[kc + 4]);
        }
        #pragma unroll
        for (int mt = 0; mt < 4; mt++)
            #pragma unroll
            for (int nt = 0; nt < 4; nt++) mma8(c[mt][nt], af[mt], bf[nt]);
    }
    __syncthreads();
    // dump C0 -> s_c (cols 0..127)
    #pragma unroll
    for (int mt = 0; mt < 4; mt++)
        #pragma unroll
        for (int nt = 0; nt < 4; nt++) {
            int row = warpM * 64 + mt * 16 + (lane >> 2);
            int col = warpN * 32 + nt * 8 + 2 * (lane & 3);
            *(float2*)(s_c + row * PAD + col)       = make_float2(c[mt][nt][0], c[mt][nt][1]);
            *(float2*)(s_c + (row + 8) * PAD + col) = make_float2(c[mt][nt][2], c[mt][nt][3]);
        }
    // stage B half1 (wpack rows 128..255: i_n | h_n)
    for (int i = tid; i < 128 * 32; i += 256) {
        int row = i >> 5, q = i & 31;
        *(float4*)(s_b + row * PAD + q * 4) = ((const float4*)wpack)[(128 + row) * 32 + q];
    }
    __syncthreads();
    // ================= MMA1 half 1 (cols 128..255: i_n | h_n) =================
    #pragma unroll
    for (int mt = 0; mt < 4; mt++)
        #pragma unroll
        for (int nt = 0; nt < 4; nt++)
            #pragma unroll
            for (int i = 0; i < 4; i++) c[mt][nt][i] = 0.f;
    #pragma unroll 4
    for (int kt = 0; kt < 16; kt++) {
        int kc = kt * 8 + (lane & 3);
        uint32_t af[4][4], bf[4][2];
        #pragma unroll
        for (int mt = 0; mt < 4; mt++) {
            const float* pa = s_a + (warpM * 64 + mt * 16 + (lane >> 2)) * PAD;
            af[mt][0] = __float_as_uint(pa[kc]);
            af[mt][1] = __float_as_uint(pa[8 * PAD + kc]);
            af[mt][2] = __float_as_uint(pa[kc + 4]);
            af[mt][3] = __float_as_uint(pa[8 * PAD + kc + 4]);
        }
        #pragma unroll
        for (int nt = 0; nt < 4; nt++) {
            const float* pb = s_b + (warpN * 32 + nt * 8 + (lane >> 2)) * PAD;
            bf[nt][0] = __float_as_uint(pb[kc]);
            bf[nt][1] = __float_as_uint(pb[kc + 4]);
        }
        #pragma unroll
        for (int mt = 0; mt < 4; mt++)
            #pragma unroll
            for (int nt = 0; nt < 4; nt++) mma8(c[mt][nt], af[mt], bf[nt]);
    }
    __syncthreads();
    // dump C1 -> s_b: local cols 0..127 = [i_n | h_n]
    #pragma unroll
    for (int mt = 0; mt < 4; mt++)
        #pragma unroll
        for (int nt = 0; nt < 4; nt++) {
            int row = warpM * 64 + mt * 16 + (lane >> 2);
            int col = warpN * 32 + nt * 8 + 2 * (lane & 3);
            *(float2*)(s_b + row * PAD + col)       = make_float2(c[mt][nt][0], c[mt][nt][1]);
            *(float2*)(s_b + (row + 8) * PAD + col) = make_float2(c[mt][nt][2], c[mt][nt][3]);
        }
    __syncthreads();

    // ================= GRU epilogue =================
    {
        int row = tid >> 1, cb = (tid & 1) * 32;
        int node = base + row;
        int nclamp = node < N_NODES ? node : N_NODES - 1;
        const float4* hg = (const float4*)(h + (size_t)nclamp * HID + cb);
        float4* ho = (float4*)(h + (size_t)node * HID + cb);
        const float* rs = s_c + row * PAD;
        const float* ih = s_b + row * PAD;
        #pragma unroll
        for (int q = 0; q < 8; q++) {
            float4 hold = hg[q];
            float hn4[4];
            #pragma unroll
            for (int e = 0; e < 4; e++) {
                int j = cb + q * 4 + e;
                float hv = (e == 0) ? hold.x : (e == 1) ? hold.y : (e == 2) ? hold.z : hold.w;
                float r = sigm(rs[j] + sb[j]);
                float z = sigm(rs[64 + j] + sb[64 + j]);
                float n = tanh_f(ih[j] + sb[128 + j] + r * (ih[64 + j] + sb[192 + j]));
                hn4[e] = (1.f - z) * n + z * hv;
            }
            if (node < N_NODES)
                ho[q] = make_float4(hn4[0], hn4[1], hn4[2], hn4[3]);
            float* da = s_a + row * PAD + cb + q * 4;
            da[0] = tf32f(hn4[0]); da[1] = tf32f(hn4[1]); da[2] = tf32f(hn4[2]); da[3] = tf32f(hn4[3]);
        }
    }
    __syncthreads();

    if (!has_next) return;

    // stage B2 = WgT (64x64) into s_b
    for (int i = tid; i < 64 * 16; i += 256) {
        int row = i >> 4, q = i & 15;
        *(float4*)(s_b + row * PAD + q * 4) = ((const float4*)wgT)[row * 16 + q];
    }
    __syncthreads();

    // ================= MMA2: m = h_new @ WgT, M=128 N=64 K=64 =================
    {
        float c2[8][4];
        #pragma unroll
        for (int nt = 0; nt < 8; nt++)
            #pragma unroll
            for (int i = 0; i < 4; i++) c2[nt][i] = 0.f;
        #pragma unroll
        for (int kt = 0; kt < 8; kt++) {
            int kc = kt * 8 + (lane & 3);
            const float* pa = s_a + (wid * 16 + (lane >> 2)) * PAD;
            uint32_t af[4];
            af[0] = __float_as_uint(pa[kc]);
            af[1] = __float_as_uint(pa[8 * PAD + kc]);
            af[2] = __float_as_uint(pa[kc + 4]);
            af[3] = __float_as_uint(pa[8 * PAD + kc + 4]);
            uint32_t bf[8][2];
            #pragma unroll
            for (int nt = 0; nt < 8; nt++) {
                const float* pb = s_b + (nt * 8 + (lane >> 2)) * PAD;
                bf[nt][0] = __float_as_uint(pb[kc]);
                bf[nt][1] = __float_as_uint(pb[kc + 4]);
            }
            #pragma unroll
            for (int nt = 0; nt < 8; nt++) mma8(c2[nt], af, bf[nt]);
        }
        __syncthreads();
        #pragma unroll
        for (int nt = 0; nt < 8; nt++) {
            int row = wid * 16 + (lane >> 2);
            int col = nt * 8 + 2 * (lane & 3);
            *(float2*)(s_c + row * PAD + col)       = make_float2(c2[nt][0], c2[nt][1]);
            *(float2*)(s_c + (row + 8) * PAD + col) = make_float2(c2[nt][2], c2[nt][3]);
        }
    }
    __syncthreads();

    // coalesced writeout: m + zero aggr
    {
        int row = tid >> 1, cb = (tid & 1) * 32;
        int node = base + row;
        if (node < N_NODES) {
            float4* mo = (float4*)(m + (size_t)node * HID + cb);
            float4* ao = (float4*)(aggr + (size_t)node * HID + cb);
            const float* sc = s_c + row * PAD + cb;
            const float4 z4 = make_float4(0.f, 0.f, 0.f, 0.f);
            #pragma unroll
            for (int q = 0; q < 8; q++) {
                mo[q] = make_float4(sc[q * 4], sc[q * 4 + 1], sc[q * 4 + 2], sc[q * 4 + 3]);
                ao[q] = z4;
            }
        }
    }
}

// =====================================================================
// select + head
// =====================================================================
__global__ __launch_bounds__(256) void select_kernel(
    const float* __restrict__ h, const int* __restrict__ idx,
    const float* __restrict__ W, const float* __restrict__ bl,
    float* __restrict__ out) {
    int g = blockIdx.x * blockDim.x + threadIdx.x;
    int w = g >> 5, lane = g & 31;
    if (w >= N_IDX) return;
    int node = idx[w];
    const float* hr = h + (size_t)node * HID;
    float s = hr[lane] * W[lane] + hr[32 + lane] * W[32 + lane];
    #pragma unroll
    for (int o = 16; o; o >>= 1) s += __shfl_xor_sync(0xffffffffu, s, o);
    if (lane == 0) out[w] = sigm(s + bl[0]);
}

// =====================================================================
extern "C" void kernel_launch(void* const* d_in, const int* in_sizes, int n_in,
                              void* d_out, int out_size) {
    const float* x        = (const float*)d_in[0];
    const int*   ei       = (const int*)d_in[1];
    const int*   idx      = (const int*)d_in[2];
    const float* W_red    = (const float*)d_in[3];
    const float* b_red    = (const float*)d_in[4];
    const float* W_g      = (const float*)d_in[5];
    const float* w_ih     = (const float*)d_in[6];
    const float* w_hh     = (const float*)d_in[7];
    const float* b_ih     = (const float*)d_in[8];
    const float* b_hh     = (const float*)d_in[9];
    const float* W_lin    = (const float*)d_in[10];
    const float* b_lin    = (const float*)d_in[11];
    float* out = (float*)d_out;

    void *ph, *pm, *pa, *pw, *pg;
    cudaGetSymbolAddress(&ph, g_h);
    cudaGetSymbolAddress(&pm, g_m);
    cudaGetSymbolAddress(&pa, g_aggr);
    cudaGetSymbolAddress(&pw, g_wpack);
    cudaGetSymbolAddress(&pg, g_wgT);
    float* h_p  = (float*)ph;
    float* m_p  = (float*)pm;
    float* a_p  = (float*)pa;
    float* wp_p = (float*)pw;
    float* wg_p = (float*)pg;

    const int RED_SMEM = ANNOT * HID * 4 + RNW * RNT * ANNOT * 8;
    const int TR_SMEM  = HID * HID * 4 + TNW * TNT * HID * 8;
    cudaFuncSetAttribute(reduce_kernel,    cudaFuncAttributeMaxDynamicSharedMemorySize, RED_SMEM);
    cudaFuncSetAttribute(transform_kernel, cudaFuncAttributeMaxDynamicSharedMemorySize, TR_SMEM);
    cudaFuncSetAttribute(gru_tc_kernel,    cudaFuncAttributeMaxDynamicSharedMemorySize, SM_TOTAL);

    pack_kernel<<<(256 * 128 + N_STEPS * 64 * 64 + 255) / 256, 256>>>(w_ih, w_hh, W_g);
    reduce_kernel<<<592, 512, RED_SMEM>>>(x, W_red, b_red, h_p);
    transform_kernel<<<592, 512, TR_SMEM>>>(h_p, W_g, m_p, a_p);
    for (int t = 0; t < N_STEPS; t++) {
        scatter_kernel<<<(N_EDGES * 16) / 256, 256>>>(m_p, ei, a_p);
        int has_next = (t < N_STEPS - 1);
        const float* wgt = wg_p + (size_t)(has_next ? t + 1 : 0) * HID * HID;
        gru_tc_kernel<<<N_TILES, 256, SM_TOTAL>>>(a_p, h_p, m_p, wp_p, wgt, b_ih, b_hh, has_next);
    }
    select_kernel<<<(N_IDX * 32 + 255) / 256, 256>>>(h_p, idx, W_lin, b_lin, out);
}

// round 15
// speedup vs baseline: 1.3231x; 1.3231x over previous
#include <cuda_runtime.h>
#include <cstdint>

#define N_NODES 100000
#define N_EDGES 800000
#define ANNOT 92
#define HID 64
#define N_STEPS 8
#define N_IDX 20000
#define TILE_M 128
#define N_TILES ((N_NODES + TILE_M - 1) / TILE_M)   // 782
#define PAD 132

typedef unsigned long long u64;

// ---- scratch (no allocations allowed) ----
__device__ float g_h[N_NODES * HID];
__device__ float g_m[N_NODES * HID];
__device__ float g_aggr[N_NODES * HID];
__device__ float g_wpack[256 * 128];         // [n=256][k=128], tf32-rounded
__device__ float g_wgT[N_STEPS * HID * HID]; // [t][n=64][k=64] = Wg^T, tf32-rounded

// ---- helpers ----
__device__ __forceinline__ u64 ffma2(u64 a, u64 b, u64 c) {
    u64 d; asm("fma.rn.f32x2 %0, %1, %2, %3;" : "=l"(d) : "l"(a), "l"(b), "l"(c)); return d;
}
__device__ __forceinline__ u64 dup2(float v) {
    unsigned u = __float_as_uint(v); u64 d;
    asm("mov.b64 %0, {%1, %2};" : "=l"(d) : "r"(u), "r"(u)); return d;
}
__device__ __forceinline__ float lo2(u64 v) { return __uint_as_float((unsigned)v); }
__device__ __forceinline__ float hi2(u64 v) { return __uint_as_float((unsigned)(v >> 32)); }
__device__ __forceinline__ float sigm(float x) { return 1.f / (1.f + __expf(-x)); }
__device__ __forceinline__ float tanh_f(float x) { return 1.f - 2.f / (__expf(2.f * x) + 1.f); }
__device__ __forceinline__ uint32_t tf32r(float f) {
    uint32_t u; asm("cvt.rna.tf32.f32 %0, %1;" : "=r"(u) : "f"(f)); return u;
}
__device__ __forceinline__ float tf32f(float f) { return __uint_as_float(tf32r(f)); }

// m16n8k8 tf32 mma: C(4 f32) += A(4 b32) * B(2 b32)
__device__ __forceinline__ void mma8(float* c, const uint32_t* a, const uint32_t* b) {
    asm("mma.sync.aligned.m16n8k8.row.col.f32.tf32.tf32.f32 "
        "{%0,%1,%2,%3}, {%4,%5,%6,%7}, {%8,%9}, {%0,%1,%2,%3};"
        : "+f"(c[0]), "+f"(c[1]), "+f"(c[2]), "+f"(c[3])
        : "r"(a[0]), "r"(a[1]), "r"(a[2]), "r"(a[3]), "r"(b[0]), "r"(b[1]));
}

// =====================================================================
// pack: g_wpack [r|z|i_n|h_n](256)x(k=128=[ih|hh]), g_wgT (tf32-rounded)
// =====================================================================
__global__ void pack_kernel(const float* __restrict__ w_ih, const float* __restrict__ w_hh,
                            const float* __restrict__ W_g) {
    int i = blockIdx.x * blockDim.x + threadIdx.x;
    if (i < 256 * 128) {
        int n = i >> 7, k = i & 127;
        float v = 0.f;
        if (n < 64)        v = (k < 64) ? w_ih[n * 64 + k]            : w_hh[n * 64 + (k - 64)];
        else if (n < 128)  { int j = n - 64;  v = (k < 64) ? w_ih[(64 + j) * 64 + k] : w_hh[(64 + j) * 64 + (k - 64)]; }
        else if (n < 192)  { int j = n - 128; v = (k < 64) ? w_ih[(128 + j) * 64 + k] : 0.f; }
        else               { int j = n - 192; v = (k < 64) ? 0.f : w_hh[(128 + j) * 64 + (k - 64)]; }
        g_wpack[i] = tf32f(v);
    }
    int i2 = i - 256 * 128;
    if (i2 >= 0 && i2 < N_STEPS * 64 * 64) {
        int t = i2 >> 12, r = i2 & 4095, n = r >> 6, k = r & 63;
        g_wgT[i2] = tf32f(W_g[t * 4096 + k * 64 + n]);
    }
}

// =====================================================================
// reduce: h = x @ W_red + b_red  (FFMA2 path)
// =====================================================================
#define RNW 16
#define RNT 2
__global__ __launch_bounds__(512) void reduce_kernel(
    const float* __restrict__ x, const float* __restrict__ W,
    const float* __restrict__ b, float* __restrict__ h) {
    extern __shared__ char smraw[];
    float* s_w = (float*)smraw;
    u64* s_x = (u64*)(s_w + ANNOT * HID);
    int tid = threadIdx.x, lane = tid & 31, warp = tid >> 5;
    for (int i = tid; i < ANNOT * HID; i += blockDim.x) s_w[i] = W[i];
    __syncthreads();
    u64* my_x = s_x + warp * (RNT * ANNOT);
    int j0 = lane * 2;
    u64 bias = *(const u64*)(b + j0);
    int stride = gridDim.x * RNW * RNT;
    for (int base = (blockIdx.x * RNW + warp) * RNT; base < N_NODES; base += stride) {
        for (int t = 0; t < RNT; t++) {
            int node = base + t; if (node >= N_NODES) node = N_NODES - 1;
            const float* xr = x + (size_t)node * ANNOT;
            my_x[t * ANNOT + lane]      = dup2(xr[lane]);
            my_x[t * ANNOT + 32 + lane] = dup2(xr[32 + lane]);
            if (lane < ANNOT - 64) my_x[t * ANNOT + 64 + lane] = dup2(xr[64 + lane]);
        }
        __syncwarp();
        u64 acc[RNT];
        #pragma unroll
        for (int t = 0; t < RNT; t++) acc[t] = bias;
        #pragma unroll 4
        for (int k = 0; k < ANNOT; k++) {
            u64 w = *(const u64*)(s_w + k * HID + j0);
            #pragma unroll
            for (int t = 0; t < RNT; t++) acc[t] = ffma2(my_x[t * ANNOT + k], w, acc[t]);
        }
        #pragma unroll
        for (int t = 0; t < RNT; t++) {
            int node = base + t;
            if (node < N_NODES)
                *(float2*)(h + (size_t)node * HID + j0) = make_float2(lo2(acc[t]), hi2(acc[t]));
        }
        __syncwarp();
    }
}

// =====================================================================
// transform0: m = h @ W_g[0], zero aggr (step 0 only; FFMA2)
// =====================================================================
#define TNW 16
#define TNT 4
__global__ __launch_bounds__(512) void transform_kernel(
    const float* __restrict__ h, const float* __restrict__ Wg,
    float* __restrict__ m, float* __restrict__ aggr) {
    extern __shared__ char smraw[];
    float* s_w = (float*)smraw;
    u64* s_h = (u64*)(s_w + HID * HID);
    int tid = threadIdx.x, lane = tid & 31, warp = tid >> 5;
    for (int i = tid; i < HID * HID; i += blockDim.x) s_w[i] = Wg[i];
    __syncthreads();
    u64* my_h = s_h + warp * (TNT * HID);
    int j0 = lane * 2;
    int stride = gridDim.x * TNW * TNT;
    for (int base = (blockIdx.x * TNW + warp) * TNT; base < N_NODES; base += stride) {
        for (int t = 0; t < TNT; t++) {
            int node = base + t; if (node >= N_NODES) node = N_NODES - 1;
            const float* hr = h + (size_t)node * HID;
            my_h[t * HID + lane]      = dup2(hr[lane]);
            my_h[t * HID + 32 + lane] = dup2(hr[32 + lane]);
        }
        __syncwarp();
        u64 acc[TNT] = {0ull, 0ull, 0ull, 0ull};
        #pragma unroll 4
        for (int k = 0; k < HID; k++) {
            u64 w = *(const u64*)(s_w + k * HID + j0);
            #pragma unroll
            for (int t = 0; t < TNT; t++) acc[t] = ffma2(my_h[t * HID + k], w, acc[t]);
        }
        #pragma unroll
        for (int t = 0; t < TNT; t++) {
            int node = base + t;
            if (node < N_NODES) {
                *(float2*)(m    + (size_t)node * HID + j0) = make_float2(lo2(acc[t]), hi2(acc[t]));
                *(float2*)(aggr + (size_t)node * HID + j0) = make_float2(0.f, 0.f);
            }
        }
        __syncwarp();
    }
}

// =====================================================================
// scatter: aggr[dst] += m[src], float4 vector atomics
// =====================================================================
__global__ __launch_bounds__(256) void scatter_kernel(
    const float* __restrict__ m, const int* __restrict__ ei,
    float* __restrict__ aggr) {
    unsigned tid = blockIdx.x * blockDim.x + threadIdx.x;
    unsigned e = tid >> 4, p = tid & 15;
    if (e >= N_EDGES) return;
    int s = ei[e];
    int d = ei[N_EDGES + e];
    float4 v = ((const float4*)(m + (size_t)s * HID))[p];
    atomicAdd((float4*)(aggr + (size_t)d * HID + p * 4), v);
}

// =====================================================================
// GRU via mma.sync tf32 — 512 threads (16 warps, 4/SMSP) for latency hiding.
// MMA1: 4x4 warp grid (2 m-tiles x 4 n-tiles per warp), two N-halves.
// MMA2: 8x2 warp grid.
// =====================================================================
#define SM_A 0
#define SM_B 67584
#define SM_C 135168
#define SM_BIAS 202752
#define SM_TOTAL 203776

__global__ __launch_bounds__(512) void gru_tc_kernel(
    float* __restrict__ aggr, float* __restrict__ h, float* __restrict__ m,
    const float* __restrict__ wpack, const float* __restrict__ wgT,
    const float* __restrict__ b_ih, const float* __restrict__ b_hh, int has_next) {
    extern __shared__ char smraw[];
    float* s_a = (float*)(smraw + SM_A);
    float* s_b = (float*)(smraw + SM_B);
    float* s_c = (float*)(smraw + SM_C);
    float* sb  = (float*)(smraw + SM_BIAS);   // [256]: r,z,i,hn biases
    int tid = threadIdx.x, lane = tid & 31, wid = tid >> 5;
    int warpM = wid >> 2, warpN = wid & 3;    // 4 x 4 warp grid for MMA1
    int base = blockIdx.x * TILE_M;

    // ---- stage A = [aggr|h] (tf32-rounded), 128x128 ----
    for (int i = tid; i < 128 * 32; i += 512) {
        int row = i >> 5, q = i & 31;
        int node = base + row; if (node >= N_NODES) node = N_NODES - 1;
        float4 v = (q < 16) ? ((const float4*)aggr)[node * 16 + q]
                            : ((const float4*)h)[node * 16 + (q - 16)];
        float* dst = s_a + row * PAD + q * 4;
        dst[0] = tf32f(v.x); dst[1] = tf32f(v.y); dst[2] = tf32f(v.z); dst[3] = tf32f(v.w);
    }
    // ---- stage B half0 (wpack rows 0..127: r|z) ----
    for (int i = tid; i < 128 * 32; i += 512) {
        int row = i >> 5, q = i & 31;
        *(float4*)(s_b + row * PAD + q * 4) = ((const float4*)wpack)[row * 32 + q];
    }
    if (tid < 64) {
        sb[tid]       = b_ih[tid] + b_hh[tid];
        sb[64 + tid]  = b_ih[64 + tid] + b_hh[64 + tid];
        sb[128 + tid] = b_ih[128 + tid];
        sb[192 + tid] = b_hh[128 + tid];
    }
    __syncthreads();

    float c[2][4][4];
    // ================= MMA1 half 0 (cols 0..127: r_sum | z_sum) =================
    #pragma unroll
    for (int mt = 0; mt < 2; mt++)
        #pragma unroll
        for (int nt = 0; nt < 4; nt++)
            #pragma unroll
            for (int i = 0; i < 4; i++) c[mt][nt][i] = 0.f;
    #pragma unroll 4
    for (int kt = 0; kt < 16; kt++) {
        int kc = kt * 8 + (lane & 3);
        uint32_t af[2][4], bf[4][2];
        #pragma unroll
        for (int mt = 0; mt < 2; mt++) {
            const float* pa = s_a + (warpM * 32 + mt * 16 + (lane >> 2)) * PAD;
            af[mt][0] = __float_as_uint(pa[kc]);
            af[mt][1] = __float_as_uint(pa[8 * PAD + kc]);
            af[mt][2] = __float_as_uint(pa[kc + 4]);
            af[mt][3] = __float_as_uint(pa[8 * PAD + kc + 4]);
        }
        #pragma unroll
        for (int nt = 0; nt < 4; nt++) {
            const float* pb = s_b + (warpN * 32 + nt * 8 + (lane >> 2)) * PAD;
            bf[nt][0] = __float_as_uint(pb[kc]);
            bf[nt][1] = __float_as_uint(pb[kc + 4]);
        }
        #pragma unroll
        for (int mt = 0; mt < 2; mt++)
            #pragma unroll
            for (int nt = 0; nt < 4; nt++) mma8(c[mt][nt], af[mt], bf[nt]);
    }
    __syncthreads();
    // dump C0 -> s_c (cols 0..127)
    #pragma unroll
    for (int mt = 0; mt < 2; mt++)
        #pragma unroll
        for (int nt = 0; nt < 4; nt++) {
            int row = warpM * 32 + mt * 16 + (lane >> 2);
            int col = warpN * 32 + nt * 8 + 2 * (lane & 3);
            *(float2*)(s_c + row * PAD + col)       = make_float2(c[mt][nt][0], c[mt][nt][1]);
            *(float2*)(s_c + (row + 8) * PAD + col) = make_float2(c[mt][nt][2], c[mt][nt][3]);
        }
    // stage B half1 (wpack rows 128..255: i_n | h_n)
    for (int i = tid; i < 128 * 32; i += 512) {
        int row = i >> 5, q = i & 31;
        *(float4*)(s_b + row * PAD + q * 4) = ((const float4*)wpack)[(128 + row) * 32 + q];
    }
    __syncthreads();
    // ================= MMA1 half 1 (cols 128..255: i_n | h_n) =================
    #pragma unroll
    for (int mt = 0; mt < 2; mt++)
        #pragma unroll
        for (int nt = 0; nt < 4; nt++)
            #pragma unroll
            for (int i = 0; i < 4; i++) c[mt][nt][i] = 0.f;
    #pragma unroll 4
    for (int kt = 0; kt < 16; kt++) {
        int kc = kt * 8 + (lane & 3);
        uint32_t af[2][4], bf[4][2];
        #pragma unroll
        for (int mt = 0; mt < 2; mt++) {
            const float* pa = s_a + (warpM * 32 + mt * 16 + (lane >> 2)) * PAD;
            af[mt][0] = __float_as_uint(pa[kc]);
            af[mt][1] = __float_as_uint(pa[8 * PAD + kc]);
            af[mt][2] = __float_as_uint(pa[kc + 4]);
            af[mt][3] = __float_as_uint(pa[8 * PAD + kc + 4]);
        }
        #pragma unroll
        for (int nt = 0; nt < 4; nt++) {
            const float* pb = s_b + (warpN * 32 + nt * 8 + (lane >> 2)) * PAD;
            bf[nt][0] = __float_as_uint(pb[kc]);
            bf[nt][1] = __float_as_uint(pb[kc + 4]);
        }
        #pragma unroll
        for (int mt = 0; mt < 2; mt++)
            #pragma unroll
            for (int nt = 0; nt < 4; nt++) mma8(c[mt][nt], af[mt], bf[nt]);
    }
    __syncthreads();
    // dump C1 -> s_b: local cols 0..127 = [i_n | h_n]
    #pragma unroll
    for (int mt = 0; mt < 2; mt++)
        #pragma unroll
        for (int nt = 0; nt < 4; nt++) {
            int row = warpM * 32 + mt * 16 + (lane >> 2);
            int col = warpN * 32 + nt * 8 + 2 * (lane & 3);
            *(float2*)(s_b + row * PAD + col)       = make_float2(c[mt][nt][0], c[mt][nt][1]);
            *(float2*)(s_b + (row + 8) * PAD + col) = make_float2(c[mt][nt][2], c[mt][nt][3]);
        }
    __syncthreads();

    // ================= GRU epilogue =================
    // thread -> (row = tid/4, cols (tid&3)*16 .. +15)
    {
        int row = tid >> 2, cb = (tid & 3) * 16;
        int node = base + row;
        int nclamp = node < N_NODES ? node : N_NODES - 1;
        const float4* hg = (const float4*)(h + (size_t)nclamp * HID + cb);
        float4* ho = (float4*)(h + (size_t)node * HID + cb);
        const float* rs = s_c + row * PAD;
        const float* ih = s_b + row * PAD;
        #pragma unroll
        for (int q = 0; q < 4; q++) {
            float4 hold = hg[q];
            float hn4[4];
            #pragma unroll
            for (int e = 0; e < 4; e++) {
                int j = cb + q * 4 + e;
                float hv = (e == 0) ? hold.x : (e == 1) ? hold.y : (e == 2) ? hold.z : hold.w;
                float r = sigm(rs[j] + sb[j]);
                float z = sigm(rs[64 + j] + sb[64 + j]);
                float n = tanh_f(ih[j] + sb[128 + j] + r * (ih[64 + j] + sb[192 + j]));
                hn4[e] = (1.f - z) * n + z * hv;
            }
            if (node < N_NODES)
                ho[q] = make_float4(hn4[0], hn4[1], hn4[2], hn4[3]);
            float* da = s_a + row * PAD + cb + q * 4;
            da[0] = tf32f(hn4[0]); da[1] = tf32f(hn4[1]); da[2] = tf32f(hn4[2]); da[3] = tf32f(hn4[3]);
        }
    }
    __syncthreads();

    if (!has_next) return;

    // stage B2 = WgT (64x64) into s_b
    for (int i = tid; i < 64 * 16; i += 512) {
        int row = i >> 4, q = i & 15;
        *(float4*)(s_b + row * PAD + q * 4) = ((const float4*)wgT)[row * 16 + q];
    }
    __syncthreads();

    // ================= MMA2: m = h_new @ WgT, M=128 N=64 K=64 =================
    // 8x2 warp grid: wm = wid>>1 (1 m-tile), wn = wid&1 (4 n-tiles)
    {
        int wm = wid >> 1, wn = wid & 1;
        float c2[4][4];
        #pragma unroll
        for (int nt = 0; nt < 4; nt++)
            #pragma unroll
            for (int i = 0; i < 4; i++) c2[nt][i] = 0.f;
        #pragma unroll
        for (int kt = 0; kt < 8; kt++) {
            int kc = kt * 8 + (lane & 3);
            const float* pa = s_a + (wm * 16 + (lane >> 2)) * PAD;
            uint32_t af[4];
            af[0] = __float_as_uint(pa[kc]);
            af[1] = __float_as_uint(pa[8 * PAD + kc]);
            af[2] = __float_as_uint(pa[kc + 4]);
            af[3] = __float_as_uint(pa[8 * PAD + kc + 4]);
            uint32_t bf[4][2];
            #pragma unroll
            for (int nt = 0; nt < 4; nt++) {
                const float* pb = s_b + (wn * 32 + nt * 8 + (lane >> 2)) * PAD;
                bf[nt][0] = __float_as_uint(pb[kc]);
                bf[nt][1] = __float_as_uint(pb[kc + 4]);
            }
            #pragma unroll
            for (int nt = 0; nt < 4; nt++) mma8(c2[nt], af, bf[nt]);
        }
        __syncthreads();
        #pragma unroll
        for (int nt = 0; nt < 4; nt++) {
            int row = wm * 16 + (lane >> 2);
            int col = wn * 32 + nt * 8 + 2 * (lane & 3);
            *(float2*)(s_c + row * PAD + col)       = make_float2(c2[nt][0], c2[nt][1]);
            *(float2*)(s_c + (row + 8) * PAD + col) = make_float2(c2[nt][2], c2[nt][3]);
        }
    }
    __syncthreads();

    // coalesced writeout: m + zero aggr
    {
        int row = tid >> 2, cb = (tid & 3) * 16;
        int node = base + row;
        if (node < N_NODES) {
            float4* mo = (float4*)(m + (size_t)node * HID + cb);
            float4* ao = (float4*)(aggr + (size_t)node * HID + cb);
            const float* sc = s_c + row * PAD + cb;
            const float4 z4 = make_float4(0.f, 0.f, 0.f, 0.f);
            #pragma unroll
            for (int q = 0; q < 4; q++) {
                mo[q] = make_float4(sc[q * 4], sc[q * 4 + 1], sc[q * 4 + 2], sc[q * 4 + 3]);
                ao[q] = z4;
            }
        }
    }
}

// =====================================================================
// select + head
// =====================================================================
__global__ __launch_bounds__(256) void select_kernel(
    const float* __restrict__ h, const int* __restrict__ idx,
    const float* __restrict__ W, const float* __restrict__ bl,
    float* __restrict__ out) {
    int g = blockIdx.x * blockDim.x + threadIdx.x;
    int w = g >> 5, lane = g & 31;
    if (w >= N_IDX) return;
    int node = idx[w];
    const float* hr = h + (size_t)node * HID;
    float s = hr[lane] * W[lane] + hr[32 + lane] * W[32 + lane];
    #pragma unroll
    for (int o = 16; o; o >>= 1) s += __shfl_xor_sync(0xffffffffu, s, o);
    if (lane == 0) out[w] = sigm(s + bl[0]);
}

// =====================================================================
extern "C" void kernel_launch(void* const* d_in, const int* in_sizes, int n_in,
                              void* d_out, int out_size) {
    const float* x        = (const float*)d_in[0];
    const int*   ei       = (const int*)d_in[1];
    const int*   idx      = (const int*)d_in[2];
    const float* W_red    = (const float*)d_in[3];
    const float* b_red    = (const float*)d_in[4];
    const float* W_g      = (const float*)d_in[5];
    const float* w_ih     = (const float*)d_in[6];
    const float* w_hh     = (const float*)d_in[7];
    const float* b_ih     = (const float*)d_in[8];
    const float* b_hh     = (const float*)d_in[9];
    const float* W_lin    = (const float*)d_in[10];
    const float* b_lin    = (const float*)d_in[11];
    float* out = (float*)d_out;

    void *ph, *pm, *pa, *pw, *pg;
    cudaGetSymbolAddress(&ph, g_h);
    cudaGetSymbolAddress(&pm, g_m);
    cudaGetSymbolAddress(&pa, g_aggr);
    cudaGetSymbolAddress(&pw, g_wpack);
    cudaGetSymbolAddress(&pg, g_wgT);
    float* h_p  = (float*)ph;
    float* m_p  = (float*)pm;
    float* a_p  = (float*)pa;
    float* wp_p = (float*)pw;
    float* wg_p = (float*)pg;

    const int RED_SMEM = ANNOT * HID * 4 + RNW * RNT * ANNOT * 8;
    const int TR_SMEM  = HID * HID * 4 + TNW * TNT * HID * 8;
    cudaFuncSetAttribute(reduce_kernel,    cudaFuncAttributeMaxDynamicSharedMemorySize, RED_SMEM);
    cudaFuncSetAttribute(transform_kernel, cudaFuncAttributeMaxDynamicSharedMemorySize, TR_SMEM);
    cudaFuncSetAttribute(gru_tc_kernel,    cudaFuncAttributeMaxDynamicSharedMemorySize, SM_TOTAL);

    pack_kernel<<<(256 * 128 + N_STEPS * 64 * 64 + 255) / 256, 256>>>(w_ih, w_hh, W_g);
    reduce_kernel<<<592, 512, RED_SMEM>>>(x, W_red, b_red, h_p);
    transform_kernel<<<592, 512, TR_SMEM>>>(h_p, W_g, m_p, a_p);
    for (int t = 0; t < N_STEPS; t++) {
        scatter_kernel<<<(N_EDGES * 16) / 256, 256>>>(m_p, ei, a_p);
        int has_next = (t < N_STEPS - 1);
        const float* wgt = wg_p + (size_t)(has_next ? t + 1 : 0) * HID * HID;
        gru_tc_kernel<<<N_TILES, 512, SM_TOTAL>>>(a_p, h_p, m_p, wp_p, wgt, b_ih, b_hh, has_next);
    }
    select_kernel<<<(N_IDX * 32 + 255) / 256, 256>>>(h_p, idx, W_lin, b_lin, out);
}

// round 17
// speedup vs baseline: 1.5090x; 1.1405x over previous
#include <cuda_runtime.h>
#include <cstdint>

#define N_NODES 100000
#define N_EDGES 800000
#define ANNOT 92
#define HID 64
#define N_STEPS 8
#define N_IDX 20000
#define TILE_M 64
#define N_TILES ((N_NODES + TILE_M - 1) / TILE_M)   // 1563
#define PADB 132
#define PADH 68

typedef unsigned long long u64;

// ---- scratch (no allocations allowed) ----
__device__ float g_h[N_NODES * HID];
__device__ float g_m[N_NODES * HID];
__device__ float g_aggr[N_NODES * HID];
__device__ float g_wpack[256 * 128];         // gate-major [r|z|i|hn] x k=[ih|hh], tf32
__device__ float g_wgT[N_STEPS * HID * HID]; // [t][n][k] = Wg^T, tf32

// ---- helpers ----
__device__ __forceinline__ u64 ffma2(u64 a, u64 b, u64 c) {
    u64 d; asm("fma.rn.f32x2 %0, %1, %2, %3;" : "=l"(d) : "l"(a), "l"(b), "l"(c)); return d;
}
__device__ __forceinline__ u64 dup2(float v) {
    unsigned u = __float_as_uint(v); u64 d;
    asm("mov.b64 %0, {%1, %2};" : "=l"(d) : "r"(u), "r"(u)); return d;
}
__device__ __forceinline__ float lo2(u64 v) { return __uint_as_float((unsigned)v); }
__device__ __forceinline__ float hi2(u64 v) { return __uint_as_float((unsigned)(v >> 32)); }
__device__ __forceinline__ float sigm(float x) { return 1.f / (1.f + __expf(-x)); }
__device__ __forceinline__ float tanh_f(float x) { return 1.f - 2.f / (__expf(2.f * x) + 1.f); }
__device__ __forceinline__ uint32_t tf32r(float f) {
    uint32_t u; asm("cvt.rna.tf32.f32 %0, %1;" : "=r"(u) : "f"(f)); return u;
}
__device__ __forceinline__ float tf32f(float f) { return __uint_as_float(tf32r(f)); }

__device__ __forceinline__ void mma8(float* c, const uint32_t* a, const uint32_t* b) {
    asm("mma.sync.aligned.m16n8k8.row.col.f32.tf32.tf32.f32 "
        "{%0,%1,%2,%3}, {%4,%5,%6,%7}, {%8,%9}, {%0,%1,%2,%3};"
        : "+f"(c[0]), "+f"(c[1]), "+f"(c[2]), "+f"(c[3])
        : "r"(a[0]), "r"(a[1]), "r"(a[2]), "r"(a[3]), "r"(b[0]), "r"(b[1]));
}

// =====================================================================
// pack (tf32-rounded weights)
// =====================================================================
__global__ void pack_kernel(const float* __restrict__ w_ih, const float* __restrict__ w_hh,
                            const float* __restrict__ W_g) {
    int i = blockIdx.x * blockDim.x + threadIdx.x;
    if (i < 256 * 128) {
        int n = i >> 7, k = i & 127;
        float v = 0.f;
        if (n < 64)        v = (k < 64) ? w_ih[n * 64 + k]            : w_hh[n * 64 + (k - 64)];
        else if (n < 128)  { int j = n - 64;  v = (k < 64) ? w_ih[(64 + j) * 64 + k] : w_hh[(64 + j) * 64 + (k - 64)]; }
        else if (n < 192)  { int j = n - 128; v = (k < 64) ? w_ih[(128 + j) * 64 + k] : 0.f; }
        else               { int j = n - 192; v = (k < 64) ? 0.f : w_hh[(128 + j) * 64 + (k - 64)]; }
        g_wpack[i] = tf32f(v);
    }
    int i2 = i - 256 * 128;
    if (i2 >= 0 && i2 < N_STEPS * 64 * 64) {
        int t = i2 >> 12, r = i2 & 4095, n = r >> 6, k = r & 63;
        g_wgT[i2] = tf32f(W_g[t * 4096 + k * 64 + n]);
    }
}

// =====================================================================
// reduce: h = x @ W_red + b_red  (FFMA2)
// =====================================================================
#define RNW 16
#define RNT 2
__global__ __launch_bounds__(512) void reduce_kernel(
    const float* __restrict__ x, const float* __restrict__ W,
    const float* __restrict__ b, float* __restrict__ h) {
    extern __shared__ char smraw[];
    float* s_w = (float*)smraw;
    u64* s_x = (u64*)(s_w + ANNOT * HID);
    int tid = threadIdx.x, lane = tid & 31, warp = tid >> 5;
    for (int i = tid; i < ANNOT * HID; i += blockDim.x) s_w[i] = W[i];
    __syncthreads();
    u64* my_x = s_x + warp * (RNT * ANNOT);
    int j0 = lane * 2;
    u64 bias = *(const u64*)(b + j0);
    int stride = gridDim.x * RNW * RNT;
    for (int base = (blockIdx.x * RNW + warp) * RNT; base < N_NODES; base += stride) {
        for (int t = 0; t < RNT; t++) {
            int node = base + t; if (node >= N_NODES) node = N_NODES - 1;
            const float* xr = x + (size_t)node * ANNOT;
            my_x[t * ANNOT + lane]      = dup2(xr[lane]);
            my_x[t * ANNOT + 32 + lane] = dup2(xr[32 + lane]);
            if (lane < ANNOT - 64) my_x[t * ANNOT + 64 + lane] = dup2(xr[64 + lane]);
        }
        __syncwarp();
        u64 acc[RNT];
        #pragma unroll
        for (int t = 0; t < RNT; t++) acc[t] = bias;
        #pragma unroll 4
        for (int k = 0; k < ANNOT; k++) {
            u64 w = *(const u64*)(s_w + k * HID + j0);
            #pragma unroll
            for (int t = 0; t < RNT; t++) acc[t] = ffma2(my_x[t * ANNOT + k], w, acc[t]);
        }
        #pragma unroll
        for (int t = 0; t < RNT; t++) {
            int node = base + t;
            if (node < N_NODES)
                *(float2*)(h + (size_t)node * HID + j0) = make_float2(lo2(acc[t]), hi2(acc[t]));
        }
        __syncwarp();
    }
}

// =====================================================================
// transform0: m = h @ W_g[0], zero aggr (step 0 only; FFMA2)
// =====================================================================
#define TNW 16
#define TNT 4
__global__ __launch_bounds__(512) void transform_kernel(
    const float* __restrict__ h, const float* __restrict__ Wg,
    float* __restrict__ m, float* __restrict__ aggr) {
    extern __shared__ char smraw[];
    float* s_w = (float*)smraw;
    u64* s_h = (u64*)(s_w + HID * HID);
    int tid = threadIdx.x, lane = tid & 31, warp = tid >> 5;
    for (int i = tid; i < HID * HID; i += blockDim.x) s_w[i] = Wg[i];
    __syncthreads();
    u64* my_h = s_h + warp * (TNT * HID);
    int j0 = lane * 2;
    int stride = gridDim.x * TNW * TNT;
    for (int base = (blockIdx.x * TNW + warp) * TNT; base < N_NODES; base += stride) {
        for (int t = 0; t < TNT; t++) {
            int node = base + t; if (node >= N_NODES) node = N_NODES - 1;
            const float* hr = h + (size_t)node * HID;
            my_h[t * HID + lane]      = dup2(hr[lane]);
            my_h[t * HID + 32 + lane] = dup2(hr[32 + lane]);
        }
        __syncwarp();
        u64 acc[TNT] = {0ull, 0ull, 0ull, 0ull};
        #pragma unroll 4
        for (int k = 0; k < HID; k++) {
            u64 w = *(const u64*)(s_w + k * HID + j0);
            #pragma unroll
            for (int t = 0; t < TNT; t++) acc[t] = ffma2(my_h[t * HID + k], w, acc[t]);
        }
        #pragma unroll
        for (int t = 0; t < TNT; t++) {
            int node = base + t;
            if (node < N_NODES) {
                *(float2*)(m    + (size_t)node * HID + j0) = make_float2(lo2(acc[t]), hi2(acc[t]));
                *(float2*)(aggr + (size_t)node * HID + j0) = make_float2(0.f, 0.f);
            }
        }
        __syncwarp();
    }
}

// =====================================================================
// scatter: aggr[dst] += m[src], float4 vector atomics
// =====================================================================
__global__ __launch_bounds__(256) void scatter_kernel(
    const float* __restrict__ m, const int* __restrict__ ei,
    float* __restrict__ aggr) {
    unsigned tid = blockIdx.x * blockDim.x + threadIdx.x;
    unsigned e = tid >> 4, p = tid & 15;
    if (e >= N_EDGES) return;
    int s = ei[e];
    int d = ei[N_EDGES + e];
    float4 v = ((const float4*)(m + (size_t)s * HID))[p];
    atomicAdd((float4*)(aggr + (size_t)d * HID + p * 4), v);
}

// =====================================================================
// GRU tensor-core kernel, 2 CTAs/SM version:
//  TILE_M=64, 256 threads (8 warps, 4M x 2N grid), smem 86KB.
//  B staged one gate-quarter at a time; per-gate C kept in registers
//  (same fragment span across gates) -> epilogue runs on fragments.
// =====================================================================
#define SM2_A 0                          // 64 x PADB floats  (33792 B)
#define SM2_B (64 * PADB * 4)            // 64 x PADB floats  (33792 B)
#define SM2_HN (2 * 64 * PADB * 4)       // 64 x PADH floats  (17408 B)
#define SM2_BIAS (SM2_HN + 64 * PADH * 4)
#define SM2_TOTAL (SM2_BIAS + 256 * 4)   // 86016 B

__global__ __launch_bounds__(256, 2) void gru_tc_kernel(
    float* __restrict__ aggr, float* __restrict__ h, float* __restrict__ m,
    const float* __restrict__ wpack, const float* __restrict__ wgT,
    const float* __restrict__ b_ih, const float* __restrict__ b_hh, int has_next) {
    extern __shared__ char smraw[];
    float* s_a  = (float*)(smraw + SM2_A);
    float* s_b  = (float*)(smraw + SM2_B);
    float* s_hn = (float*)(smraw + SM2_HN);
    float* sb   = (float*)(smraw + SM2_BIAS);
    int tid = threadIdx.x, lane = tid & 31, wid = tid >> 5;
    int warpM = wid >> 1, warpN = wid & 1;     // 4 x 2 warp grid
    int tg = lane & 3, gp = lane >> 2;
    int base = blockIdx.x * TILE_M;

    // ---- stage A = [aggr|h] (tf32), 64x128 ----
    for (int i = tid; i < 64 * 32; i += 256) {
        int row = i >> 5, q = i & 31;
        int node = base + row; if (node >= N_NODES) node = N_NODES - 1;
        float4 v = (q < 16) ? ((const float4*)aggr)[node * 16 + q]
                            : ((const float4*)h)[node * 16 + (q - 16)];
        float* dst = s_a + row * PADB + q * 4;
        dst[0] = tf32f(v.x); dst[1] = tf32f(v.y); dst[2] = tf32f(v.z); dst[3] = tf32f(v.w);
    }
    if (tid < 64) {
        sb[tid]       = b_ih[tid] + b_hh[tid];
        sb[64 + tid]  = b_ih[64 + tid] + b_hh[64 + tid];
        sb[128 + tid] = b_ih[128 + tid];
        sb[192 + tid] = b_hh[128 + tid];
    }

    // ---- MMA1: 4 gate quarters, C per gate kept in registers ----
    float c[4][4][4];
    #pragma unroll
    for (int g = 0; g < 4; g++)
        #pragma unroll
        for (int nt = 0; nt < 4; nt++)
            #pragma unroll
            for (int i = 0; i < 4; i++) c[g][nt][i] = 0.f;

    int arow = warpM * 16 + gp;
    #pragma unroll
    for (int g = 0; g < 4; g++) {
        __syncthreads();   // previous MMA pass done reading s_b (and A staged on g=0)
        for (int i = tid; i < 64 * 32; i += 256) {
            int row = i >> 5, q = i & 31;
            *(float4*)(s_b + row * PADB + q * 4) = ((const float4*)wpack)[(g * 64 + row) * 32 + q];
        }
        __syncthreads();
        #pragma unroll 4
        for (int kt = 0; kt < 16; kt++) {
            int kc = kt * 8 + tg;
            const float* pa = s_a + arow * PADB;
            uint32_t af[4];
            af[0] = __float_as_uint(pa[kc]);
            af[1] = __float_as_uint(pa[8 * PADB + kc]);
            af[2] = __float_as_uint(pa[kc + 4]);
            af[3] = __float_as_uint(pa[8 * PADB + kc + 4]);
            uint32_t bf[4][2];
            #pragma unroll
            for (int nt = 0; nt < 4; nt++) {
                const float* pb = s_b + (warpN * 32 + nt * 8 + gp) * PADB;
                bf[nt][0] = __float_as_uint(pb[kc]);
                bf[nt][1] = __float_as_uint(pb[kc + 4]);
            }
            #pragma unroll
            for (int nt = 0; nt < 4; nt++) mma8(c[g][nt], af, bf[nt]);
        }
    }

    // ---- GRU epilogue on fragments ----
    #pragma unroll
    for (int nt = 0; nt < 4; nt++) {
        int col = warpN * 32 + nt * 8 + 2 * tg;
        #pragma unroll
        for (int rr = 0; rr < 2; rr++) {
            int row = arow + rr * 8;
            int node = base + row;
            int nclamp = node < N_NODES ? node : N_NODES - 1;
            float2 hold = *(const float2*)(h + (size_t)nclamp * HID + col);
            int c0 = rr * 2, c1 = rr * 2 + 1;
            float r0 = sigm(c[0][nt][c0] + sb[col]);
            float r1 = sigm(c[0][nt][c1] + sb[col + 1]);
            float z0 = sigm(c[1][nt][c0] + sb[64 + col]);
            float z1 = sigm(c[1][nt][c1] + sb[64 + col + 1]);
            float n0 = tanh_f(c[2][nt][c0] + sb[128 + col] + r0 * (c[3][nt][c0] + sb[192 + col]));
            float n1 = tanh_f(c[2][nt][c1] + sb[128 + col + 1] + r1 * (c[3][nt][c1] + sb[192 + col + 1]));
            float h0 = (1.f - z0) * n0 + z0 * hold.x;
            float h1 = (1.f - z1) * n1 + z1 * hold.y;
            if (node < N_NODES)
                *(float2*)(h + (size_t)node * HID + col) = make_float2(h0, h1);
            *(float2*)(s_hn + row * PADH + col) = make_float2(tf32f(h0), tf32f(h1));
        }
    }

    if (!has_next) return;
    __syncthreads();    // s_hn complete; s_b free (last MMA1 pass done)

    // ---- stage B2 = wgT (64x64) ----
    for (int i = tid; i < 64 * 16; i += 256) {
        int row = i >> 4, q = i & 15;
        *(float4*)(s_b + row * PADB + q * 4) = ((const float4*)wgT)[row * 16 + q];
    }
    __syncthreads();

    // ---- MMA2: m = h_new @ WgT (M=64, N=64, K=64) ----
    float c2[4][4];
    #pragma unroll
    for (int nt = 0; nt < 4; nt++)
        #pragma unroll
        for (int i = 0; i < 4; i++) c2[nt][i] = 0.f;
    #pragma unroll
    for (int kt = 0; kt < 8; kt++) {
        int kc = kt * 8 + tg;
        const float* pa = s_hn + arow * PADH;
        uint32_t af[4];
        af[0] = __float_as_uint(pa[kc]);
        af[1] = __float_as_uint(pa[8 * PADH + kc]);
        af[2] = __float_as_uint(pa[kc + 4]);
        af[3] = __float_as_uint(pa[8 * PADH + kc + 4]);
        uint32_t bf[4][2];
        #pragma unroll
        for (int nt = 0; nt < 4; nt++) {
            const float* pb = s_b + (warpN * 32 + nt * 8 + gp) * PADB;
            bf[nt][0] = __float_as_uint(pb[kc]);
            bf[nt][1] = __float_as_uint(pb[kc + 4]);
        }
        #pragma unroll
        for (int nt = 0; nt < 4; nt++) mma8(c2[nt], af, bf[nt]);
    }
    // write m from fragments
    #pragma unroll
    for (int nt = 0; nt < 4; nt++) {
        int col = warpN * 32 + nt * 8 + 2 * tg;
        #pragma unroll
        for (int rr = 0; rr < 2; rr++) {
            int row = arow + rr * 8;
            int node = base + row;
            if (node < N_NODES)
                *(float2*)(m + (size_t)node * HID + col) =
                    make_float2(c2[nt][rr * 2], c2[nt][rr * 2 + 1]);
        }
    }
    // zero aggr (coalesced)
    const float4 z4 = make_float4(0.f, 0.f, 0.f, 0.f);
    for (int i = tid; i < 64 * 16; i += 256) {
        int row = i >> 4, q = i & 15;
        int node = base + row;
        if (node < N_NODES) ((float4*)aggr)[node * 16 + q] = z4;
    }
}

// =====================================================================
// select + head
// =====================================================================
__global__ __launch_bounds__(256) void select_kernel(
    const float* __restrict__ h, const int* __restrict__ idx,
    const float* __restrict__ W, const float* __restrict__ bl,
    float* __restrict__ out) {
    int g = blockIdx.x * blockDim.x + threadIdx.x;
    int w = g >> 5, lane = g & 31;
    if (w >= N_IDX) return;
    int node = idx[w];
    const float* hr = h + (size_t)node * HID;
    float s = hr[lane] * W[lane] + hr[32 + lane] * W[32 + lane];
    #pragma unroll
    for (int o = 16; o; o >>= 1) s += __shfl_xor_sync(0xffffffffu, s, o);
    if (lane == 0) out[w] = sigm(s + bl[0]);
}

// =====================================================================
extern "C" void kernel_launch(void* const* d_in, const int* in_sizes, int n_in,
                              void* d_out, int out_size) {
    const float* x        = (const float*)d_in[0];
    const int*   ei       = (const int*)d_in[1];
    const int*   idx      = (const int*)d_in[2];
    const float* W_red    = (const float*)d_in[3];
    const float* b_red    = (const float*)d_in[4];
    const float* W_g      = (const float*)d_in[5];
    const float* w_ih     = (const float*)d_in[6];
    const float* w_hh     = (const float*)d_in[7];
    const float* b_ih     = (const float*)d_in[8];
    const float* b_hh     = (const float*)d_in[9];
    const float* W_lin    = (const float*)d_in[10];
    const float* b_lin    = (const float*)d_in[11];
    float* out = (float*)d_out;

    void *ph, *pm, *pa, *pw, *pg;
    cudaGetSymbolAddress(&ph, g_h);
    cudaGetSymbolAddress(&pm, g_m);
    cudaGetSymbolAddress(&pa, g_aggr);
    cudaGetSymbolAddress(&pw, g_wpack);
    cudaGetSymbolAddress(&pg, g_wgT);
    float* h_p  = (float*)ph;
    float* m_p  = (float*)pm;
    float* a_p  = (float*)pa;
    float* wp_p = (float*)pw;
    float* wg_p = (float*)pg;

    const int RED_SMEM = ANNOT * HID * 4 + RNW * RNT * ANNOT * 8;
    const int TR_SMEM  = HID * HID * 4 + TNW * TNT * HID * 8;
    cudaFuncSetAttribute(reduce_kernel,    cudaFuncAttributeMaxDynamicSharedMemorySize, RED_SMEM);
    cudaFuncSetAttribute(transform_kernel, cudaFuncAttributeMaxDynamicSharedMemorySize, TR_SMEM);
    cudaFuncSetAttribute(gru_tc_kernel,    cudaFuncAttributeMaxDynamicSharedMemorySize, SM2_TOTAL);

    pack_kernel<<<(256 * 128 + N_STEPS * 64 * 64 + 255) / 256, 256>>>(w_ih, w_hh, W_g);
    reduce_kernel<<<592, 512, RED_SMEM>>>(x, W_red, b_red, h_p);
    transform_kernel<<<592, 512, TR_SMEM>>>(h_p, W_g, m_p, a_p);
    for (int t = 0; t < N_STEPS; t++) {
        scatter_kernel<<<(N_EDGES * 16) / 256, 256>>>(m_p, ei, a_p);
        int has_next = (t < N_STEPS - 1);
        const float* wgt = wg_p + (size_t)(has_next ? t + 1 : 0) * HID * HID;
        gru_tc_kernel<<<N_TILES, 256, SM2_TOTAL>>>(a_p, h_p, m_p, wp_p, wgt, b_ih, b_hh, has_next);
    }
    select_kernel<<<(N_IDX * 32 + 255) / 256, 256>>>(h_p, idx, W_lin, b_lin, out);
}